// round 6
// baseline (speedup 1.0000x reference)
#include <cuda_runtime.h>
#include <cstdint>

// SpikingHabenula: two Izhikevich populations, T=20 steps, output = 16 floats.
// HBM-bound: ~290 MB streaming reads (noise dominates). Strategy: state in
// registers, float4 noise loads, in-register rate reduction -> atomicAdd,
// tiny epilogue kernel for the 16 scalar outputs.

#define TPB 256

namespace sh {
constexpr int N_LHB = 2097152;
constexpr int N_MHB = 1048576;
constexpr int T     = 20;
constexpr int V4_LHB = N_LHB / 4;          // 524288
constexpr int V4_MHB = N_MHB / 4;          // 262144
constexpr int NBLK_LHB = V4_LHB / TPB;     // 2048
constexpr int NBLK_MHB = V4_MHB / TPB;     // 1024

// Izhikevich RS params
constexpr float A = 0.02f, B = 0.2f, C = -65.0f, D = 8.0f;
constexpr float V_PEAK = 30.0f;
constexpr float I_TONIC = -1.0f;
constexpr float RATE_DECAY = 0.9f;
constexpr float ONE_MINUS_DECAY = 0.1f;    // matches f32(1.0 - 0.9) in the reference
}

// Global accumulators: [0] = sum(rate_lhb_final), [1] = sum(rate_mhb_final)
__device__ float g_rate_sum[2];

__global__ void zero_sums_kernel() {
    if (threadIdx.x < 2) g_rate_sum[threadIdx.x] = 0.0f;
}

__device__ __forceinline__ void izh_step(float& v, float& u, float& r,
                                         float n, float base_I) {
    using namespace sh;
    float I  = base_I + n * 0.5f;
    float v1 = v + (0.04f * v * v + 5.0f * v + 140.0f - u + I);
    float u1 = u + A * (B * v - u);
    bool  sp = (v1 >= V_PEAK);
    v = sp ? C : v1;
    u = sp ? (u1 + D) : u1;
    r = r * RATE_DECAY + (sp ? ONE_MINUS_DECAY : 0.0f);
}

__global__ void __launch_bounds__(TPB)
sim_kernel(const float* __restrict__ reward,
           const float* __restrict__ expected_reward,
           const float* __restrict__ aversion,
           const float4* __restrict__ v_l, const float4* __restrict__ u_l,
           const float4* __restrict__ r_l, const float4* __restrict__ noise_l,
           const float4* __restrict__ v_m, const float4* __restrict__ u_m,
           const float4* __restrict__ r_m, const float4* __restrict__ noise_m)
{
    using namespace sh;
    const bool is_lhb = (blockIdx.x < (unsigned)NBLK_LHB);
    const int  bid    = is_lhb ? blockIdx.x : (blockIdx.x - NBLK_LHB);
    const int  n4     = is_lhb ? V4_LHB : V4_MHB;
    const int  idx    = bid * TPB + threadIdx.x;

    const float4* vp = is_lhb ? v_l : v_m;
    const float4* up = is_lhb ? u_l : u_m;
    const float4* rp = is_lhb ? r_l : r_m;
    const float4* np = is_lhb ? noise_l : noise_m;

    // Drive term: LHB <- disappointment*20, MHB <- aversion*15. Both read
    // device scalars (broadcast, L2-cached) so everything stays in-graph.
    float drive;
    if (is_lhb) {
        float rpe = reward[0] - expected_reward[0];
        drive = fmaxf(0.0f, -rpe) * 20.0f;
    } else {
        drive = aversion[0] * 15.0f;
    }
    const float base_I = drive + I_TONIC;

    float4 v = vp[idx];
    float4 u = up[idx];
    float4 r = rp[idx];

    #pragma unroll
    for (int t = 0; t < T; t++) {
        float4 n = np[(size_t)t * n4 + idx];
        izh_step(v.x, u.x, r.x, n.x, base_I);
        izh_step(v.y, u.y, r.y, n.y, base_I);
        izh_step(v.z, u.z, r.z, n.z, base_I);
        izh_step(v.w, u.w, r.w, n.w, base_I);
    }

    // Reduce final rate: thread -> warp -> block -> one atomicAdd per block.
    float s = (r.x + r.y) + (r.z + r.w);
    #pragma unroll
    for (int o = 16; o > 0; o >>= 1)
        s += __shfl_down_sync(0xFFFFFFFFu, s, o);

    __shared__ float warp_sums[TPB / 32];
    const int lane = threadIdx.x & 31;
    const int wid  = threadIdx.x >> 5;
    if (lane == 0) warp_sums[wid] = s;
    __syncthreads();

    if (wid == 0) {
        s = (lane < TPB / 32) ? warp_sums[lane] : 0.0f;
        #pragma unroll
        for (int o = (TPB / 64); o > 0; o >>= 1)
            s += __shfl_down_sync(0xFFFFFFFFu, s, o);
        if (lane == 0)
            atomicAdd(&g_rate_sum[is_lhb ? 0 : 1], s);
    }
}

__global__ void finalize_kernel(const float* __restrict__ reward,
                                const float* __restrict__ expected_reward,
                                const float* __restrict__ aversion,
                                const float* __restrict__ DA,
                                const int*   __restrict__ current_goal,
                                const float* __restrict__ frustration,
                                float* __restrict__ out)
{
    using namespace sh;
    if (threadIdx.x != 0 || blockIdx.x != 0) return;

    const float rpe        = reward[0] - expected_reward[0];
    const float disappoint = fmaxf(0.0f, -rpe);
    const float lhb_mean   = g_rate_sum[0] * (1.0f / (float)N_LHB);
    const float mhb_mean   = g_rate_sum[1] * (1.0f / (float)N_MHB);
    const float da_supp    = fminf(0.5f, lhb_mean * 5.0f);
    const float ht5_supp   = fminf(0.3f, lhb_mean * 3.0f);

    const int g = current_goal[0];
    float f[4];
    #pragma unroll
    for (int i = 0; i < 4; i++) f[i] = frustration[i] * 0.998f;

    f[g] += (rpe < -0.05f) ? (0.05f * fabsf(rpe)) : 0.0f;
    f[g] *= (rpe > 0.1f) ? 0.8f : 1.0f;
    #pragma unroll
    for (int i = 0; i < 4; i++) f[i] = fminf(1.0f, fmaxf(0.0f, f[i]));

    float helplessness = f[0];
    #pragma unroll
    for (int i = 1; i < 4; i++) helplessness = fmaxf(helplessness, f[i]);

    const float sw = (f[g] > 0.4f) ? 1.0f : 0.0f;
    f[g] *= (sw > 0.0f) ? 0.3f : 1.0f;

    const float dopa_mod = fmaxf(0.5f, 2.0f * (1.0f - DA[0]));
    const float explore  = fminf(1.0f, disappoint * 2.0f + lhb_mean * 3.0f);

    out[0] = disappoint;
    out[1] = da_supp;
    out[2] = ht5_supp;
    out[3] = lhb_mean;
    out[4] = mhb_mean;
    out[5] = explore;
    out[6] = helplessness;
    out[7] = sw;
    #pragma unroll
    for (int i = 0; i < 4; i++) out[8 + i]  = f[i] * 0.5f * dopa_mod;
    #pragma unroll
    for (int i = 0; i < 4; i++) out[12 + i] = f[i];
}

// Input order per metadata.txt / setup_inputs dict:
//  0 reward[1] f32, 1 expected_reward[1] f32, 2 aversion[1] f32, 3 DA[1] f32,
//  4 current_goal[1] i32, 5 frustration[4] f32,
//  6 v_lhb, 7 u_lhb, 8 rate_lhb      (N_LHB f32)
//  9 v_mhb, 10 u_mhb, 11 rate_mhb    (N_MHB f32)
// 12 noise_lhb [T*N_LHB] f32, 13 noise_mhb [T*N_MHB] f32
extern "C" void kernel_launch(void* const* d_in, const int* in_sizes, int n_in,
                              void* d_out, int out_size) {
    using namespace sh;
    const float* reward     = (const float*)d_in[0];
    const float* expected_r = (const float*)d_in[1];
    const float* aversion   = (const float*)d_in[2];
    const float* DA         = (const float*)d_in[3];
    const int*   goal       = (const int*)d_in[4];
    const float* frustr     = (const float*)d_in[5];
    const float4* v_l  = (const float4*)d_in[6];
    const float4* u_l  = (const float4*)d_in[7];
    const float4* r_l  = (const float4*)d_in[8];
    const float4* v_m  = (const float4*)d_in[9];
    const float4* u_m  = (const float4*)d_in[10];
    const float4* r_m  = (const float4*)d_in[11];
    const float4* n_l  = (const float4*)d_in[12];
    const float4* n_m  = (const float4*)d_in[13];
    float* out = (float*)d_out;

    zero_sums_kernel<<<1, 32>>>();
    sim_kernel<<<NBLK_LHB + NBLK_MHB, TPB>>>(reward, expected_r, aversion,
                                             v_l, u_l, r_l, n_l,
                                             v_m, u_m, r_m, n_m);
    finalize_kernel<<<1, 32>>>(reward, expected_r, aversion, DA, goal, frustr, out);
}

// round 10
// speedup vs baseline: 1.0074x; 1.0074x over previous
#include <cuda_runtime.h>
#include <cstdint>

// SpikingHabenula: two Izhikevich populations, T=20 steps, output = 16 floats.
// HBM-bound: ~290 MB streaming reads. Single fused kernel: state in registers,
// __ldcs float4 noise loads (read-once -> evict-first), in-register rate
// reduction -> 1 atomicAdd/block, last-block-done epilogue computes the 16
// outputs and resets accumulators for graph replay. R6 measured 51.97us with
// 3 launches (zero 3.2us + sim ~46us + finalize ~2.8us); this removes the
// two auxiliary launches.

#define TPB 256

namespace sh {
constexpr int N_LHB = 2097152;
constexpr int N_MHB = 1048576;
constexpr int T     = 20;
constexpr int V4_LHB = N_LHB / 4;          // 524288
constexpr int V4_MHB = N_MHB / 4;          // 262144
constexpr int NBLK_LHB = V4_LHB / TPB;     // 2048
constexpr int NBLK_MHB = V4_MHB / TPB;     // 1024
constexpr int NBLK_TOTAL = NBLK_LHB + NBLK_MHB;  // 3072

// Izhikevich RS params
constexpr float A = 0.02f, B = 0.2f, C = -65.0f, D = 8.0f;
constexpr float V_PEAK = 30.0f;
constexpr float I_TONIC = -1.0f;
constexpr float RATE_DECAY = 0.9f;
constexpr float ONE_MINUS_DECAY = 0.1f;
}

// Zero-initialized at module load; the last block resets them to zero after
// each call, so every invocation (and every graph replay) starts from zero.
__device__ float    g_rate_sum[2];
__device__ unsigned g_done_count;

__device__ __forceinline__ void izh_step(float& v, float& u, float& r,
                                         float n, float base_I) {
    using namespace sh;
    float I  = base_I + n * 0.5f;
    float v1 = v + (0.04f * v * v + 5.0f * v + 140.0f - u + I);
    float u1 = u + A * (B * v - u);
    bool  sp = (v1 >= V_PEAK);
    v = sp ? C : v1;
    u = sp ? (u1 + D) : u1;
    r = r * RATE_DECAY + (sp ? ONE_MINUS_DECAY : 0.0f);
}

__global__ void __launch_bounds__(TPB)
fused_kernel(const float* __restrict__ reward,
             const float* __restrict__ expected_reward,
             const float* __restrict__ aversion,
             const float* __restrict__ DA,
             const int*   __restrict__ current_goal,
             const float* __restrict__ frustration,
             const float4* __restrict__ v_l, const float4* __restrict__ u_l,
             const float4* __restrict__ r_l, const float4* __restrict__ noise_l,
             const float4* __restrict__ v_m, const float4* __restrict__ u_m,
             const float4* __restrict__ r_m, const float4* __restrict__ noise_m,
             float* __restrict__ out)
{
    using namespace sh;
    const bool is_lhb = (blockIdx.x < (unsigned)NBLK_LHB);
    const int  bid    = is_lhb ? blockIdx.x : (blockIdx.x - NBLK_LHB);
    const int  n4     = is_lhb ? V4_LHB : V4_MHB;
    const int  idx    = bid * TPB + threadIdx.x;

    const float4* vp = is_lhb ? v_l : v_m;
    const float4* up = is_lhb ? u_l : u_m;
    const float4* rp = is_lhb ? r_l : r_m;
    const float4* np = is_lhb ? noise_l : noise_m;

    // Drive term from device scalars (broadcast, L2-hit).
    float drive;
    if (is_lhb) {
        float rpe = reward[0] - expected_reward[0];
        drive = fmaxf(0.0f, -rpe) * 20.0f;
    } else {
        drive = aversion[0] * 15.0f;
    }
    const float base_I = drive + I_TONIC;

    // All bulk data is read exactly once -> streaming loads (evict-first).
    float4 v = __ldcs(&vp[idx]);
    float4 u = __ldcs(&up[idx]);
    float4 r = __ldcs(&rp[idx]);

    #pragma unroll
    for (int t = 0; t < T; t++) {
        float4 n = __ldcs(&np[(size_t)t * n4 + idx]);
        izh_step(v.x, u.x, r.x, n.x, base_I);
        izh_step(v.y, u.y, r.y, n.y, base_I);
        izh_step(v.z, u.z, r.z, n.z, base_I);
        izh_step(v.w, u.w, r.w, n.w, base_I);
    }

    // Reduce final rate: thread -> warp -> block -> one atomicAdd per block.
    float s = (r.x + r.y) + (r.z + r.w);
    #pragma unroll
    for (int o = 16; o > 0; o >>= 1)
        s += __shfl_down_sync(0xFFFFFFFFu, s, o);

    __shared__ float warp_sums[TPB / 32];
    const int lane = threadIdx.x & 31;
    const int wid  = threadIdx.x >> 5;
    if (lane == 0) warp_sums[wid] = s;
    __syncthreads();

    if (threadIdx.x < 32) {
        s = (lane < TPB / 32) ? warp_sums[lane] : 0.0f;
        #pragma unroll
        for (int o = (TPB / 64); o > 0; o >>= 1)
            s += __shfl_down_sync(0xFFFFFFFFu, s, o);
    }

    // Last-block-done epilogue (thread 0 of the final block to finish).
    if (threadIdx.x == 0) {
        atomicAdd(&g_rate_sum[is_lhb ? 0 : 1], s);
        __threadfence();
        unsigned ticket = atomicAdd(&g_done_count, 1u);
        if (ticket == (unsigned)(NBLK_TOTAL - 1)) {
            // All other blocks' sum-atomics are visible (fence before ticket).
            const float lhb_sum = g_rate_sum[0];
            const float mhb_sum = g_rate_sum[1];

            const float rpe        = reward[0] - expected_reward[0];
            const float disappoint = fmaxf(0.0f, -rpe);
            const float lhb_mean   = lhb_sum * (1.0f / (float)N_LHB);
            const float mhb_mean   = mhb_sum * (1.0f / (float)N_MHB);
            const float da_supp    = fminf(0.5f, lhb_mean * 5.0f);
            const float ht5_supp   = fminf(0.3f, lhb_mean * 3.0f);

            const int g = current_goal[0];
            float f[4];
            #pragma unroll
            for (int i = 0; i < 4; i++) f[i] = frustration[i] * 0.998f;

            f[g] += (rpe < -0.05f) ? (0.05f * fabsf(rpe)) : 0.0f;
            f[g] *= (rpe > 0.1f) ? 0.8f : 1.0f;
            #pragma unroll
            for (int i = 0; i < 4; i++) f[i] = fminf(1.0f, fmaxf(0.0f, f[i]));

            float helplessness = f[0];
            #pragma unroll
            for (int i = 1; i < 4; i++) helplessness = fmaxf(helplessness, f[i]);

            const float sw = (f[g] > 0.4f) ? 1.0f : 0.0f;
            f[g] *= (sw > 0.0f) ? 0.3f : 1.0f;

            const float dopa_mod = fmaxf(0.5f, 2.0f * (1.0f - DA[0]));
            const float explore  = fminf(1.0f, disappoint * 2.0f + lhb_mean * 3.0f);

            out[0] = disappoint;
            out[1] = da_supp;
            out[2] = ht5_supp;
            out[3] = lhb_mean;
            out[4] = mhb_mean;
            out[5] = explore;
            out[6] = helplessness;
            out[7] = sw;
            #pragma unroll
            for (int i = 0; i < 4; i++) out[8 + i]  = f[i] * 0.5f * dopa_mod;
            #pragma unroll
            for (int i = 0; i < 4; i++) out[12 + i] = f[i];

            // Reset for the next invocation / graph replay.
            g_rate_sum[0] = 0.0f;
            g_rate_sum[1] = 0.0f;
            __threadfence();
            g_done_count  = 0u;
        }
    }
}

// Input order per metadata.txt:
//  0 reward[1] f32, 1 expected_reward[1] f32, 2 aversion[1] f32, 3 DA[1] f32,
//  4 current_goal[1] i32, 5 frustration[4] f32,
//  6 v_lhb, 7 u_lhb, 8 rate_lhb      (N_LHB f32)
//  9 v_mhb, 10 u_mhb, 11 rate_mhb    (N_MHB f32)
// 12 noise_lhb [T*N_LHB] f32, 13 noise_mhb [T*N_MHB] f32
extern "C" void kernel_launch(void* const* d_in, const int* in_sizes, int n_in,
                              void* d_out, int out_size) {
    using namespace sh;
    const float* reward     = (const float*)d_in[0];
    const float* expected_r = (const float*)d_in[1];
    const float* aversion   = (const float*)d_in[2];
    const float* DA         = (const float*)d_in[3];
    const int*   goal       = (const int*)d_in[4];
    const float* frustr     = (const float*)d_in[5];
    const float4* v_l  = (const float4*)d_in[6];
    const float4* u_l  = (const float4*)d_in[7];
    const float4* r_l  = (const float4*)d_in[8];
    const float4* v_m  = (const float4*)d_in[9];
    const float4* u_m  = (const float4*)d_in[10];
    const float4* r_m  = (const float4*)d_in[11];
    const float4* n_l  = (const float4*)d_in[12];
    const float4* n_m  = (const float4*)d_in[13];
    float* out = (float*)d_out;

    fused_kernel<<<NBLK_TOTAL, TPB>>>(reward, expected_r, aversion, DA, goal,
                                      frustr,
                                      v_l, u_l, r_l, n_l,
                                      v_m, u_m, r_m, n_m,
                                      out);
}